// round 16
// baseline (speedup 1.0000x reference)
#include <cuda_runtime.h>
#include <cstdint>

#define MARGIN 0.1f
#define RPT 32                          // rows per TMA tile
#define TILE_FLOATS (RPT * 128)         // 4096
#define TILE_BYTES  (TILE_FLOATS * 4)   // 16384
#define LAB_BYTES   (RPT * 4)           // 128
#define RPB 4                           // rows per LDG batch
#define NTW 8                           // TMA consumer warps
#define NLW 2                           // LDG streamer warps
#define NWARPS (NTW + NLW)              // 10
#define NTHREADS (NWARPS * 32)          // 320
#define NUM_BLOCKS 592                  // 148 SMs * 4 CTAs, single wave

// Persistent device scratch; reset by last block each call (graph-replay safe).
__device__ double       g_total = 0.0;
__device__ unsigned int g_count = 0u;

__device__ __forceinline__ uint32_t smem_u32(const void* p) {
    return (uint32_t)__cvta_generic_to_shared(p);
}
__device__ __forceinline__ void mbar_init(uint32_t a, uint32_t cnt) {
    asm volatile("mbarrier.init.shared.b64 [%0], %1;" :: "r"(a), "r"(cnt) : "memory");
}
__device__ __forceinline__ void mbar_expect_tx(uint32_t a, uint32_t bytes) {
    asm volatile("mbarrier.arrive.expect_tx.shared.b64 _, [%0], %1;"
                 :: "r"(a), "r"(bytes) : "memory");
}
__device__ __forceinline__ void bulk_g2s(uint32_t dst, const void* src,
                                         uint32_t bytes, uint32_t mbar) {
    asm volatile(
        "cp.async.bulk.shared::cluster.global.mbarrier::complete_tx::bytes "
        "[%0], [%1], %2, [%3];"
        :: "r"(dst), "l"(src), "r"(bytes), "r"(mbar) : "memory");
}
__device__ __forceinline__ void mbar_wait(uint32_t a, uint32_t parity) {
    asm volatile(
        "{\n\t"
        ".reg .pred P;\n\t"
        "WAIT_%=:\n\t"
        "mbarrier.try_wait.parity.acquire.cta.shared::cta.b64 P, [%0], %1, 0x989680;\n\t"
        "@P bra.uni DONE_%=;\n\t"
        "bra.uni WAIT_%=;\n\t"
        "DONE_%=:\n\t"
        "}"
        :: "r"(a), "r"(parity) : "memory");
}
__device__ __forceinline__ void fence_async() {
    asm volatile("fence.proxy.async.shared::cta;" ::: "memory");
}
// Named barrier scoped to the 8 TMA consumer warps (threads 0..255).
__device__ __forceinline__ void tma_warps_sync() {
    asm volatile("bar.sync 1, 256;" ::: "memory");
}

__global__ void __launch_bounds__(NTHREADS, 4)
margin_loss_kernel(const float* __restrict__ x,
                   const int* __restrict__ labels,   // int32 (JAX x64 disabled)
                   float* __restrict__ out,
                   int N)
{
    __shared__ __align__(128) float sdata[2][TILE_FLOATS];   // 32 KB
    __shared__ __align__(16)  int   slab[2][RPT];
    __shared__ __align__(8)   unsigned long long smbar[2];
    __shared__ float warp_sums[NWARPS];
    __shared__ bool  is_last;

    const int tid  = threadIdx.x;
    const int warp = tid >> 5;
    const int lane = tid & 31;

    const int pRows = N >> 1;                        // persistent (TMA/L2) half
    const float4* x4   = reinterpret_cast<const float4*>(x);
    const int4*   lab4 = reinterpret_cast<const int4*>(labels);

    if (tid == 0) {
        mbar_init(smem_u32(&smbar[0]), 1);
        mbar_init(smem_u32(&smbar[1]), 1);
        fence_async();
    }
    __syncthreads();     // once: mbarriers visible to all warps

    float wsum  = 0.0f;
    int   nrows = 0;

    if (warp < NTW) {
        // ════ TMA consumer warps: rows [0, pRows), 2-stage pipeline ════
        const int ntT  = pRows / RPT;                             // 4096
        const int cntT = ((int)blockIdx.x < ntT)
                       ? (ntT - 1 - (int)blockIdx.x) / NUM_BLOCKS + 1 : 0;

        if (tid == 0) {     // prologue: fill both stages
            #pragma unroll
            for (int s = 0; s < 2; s++) {
                if (s < cntT) {
                    const int t = blockIdx.x + s * NUM_BLOCKS;
                    const uint32_t mb = smem_u32(&smbar[s]);
                    mbar_expect_tx(mb, TILE_BYTES + LAB_BYTES);
                    bulk_g2s(smem_u32(&sdata[s][0]),
                             x + (size_t)t * TILE_FLOATS, TILE_BYTES, mb);
                    bulk_g2s(smem_u32(&slab[s][0]),
                             labels + (size_t)t * RPT, LAB_BYTES, mb);
                }
            }
        }

        for (int k = 0; k < cntT; k++) {
            const int s = k & 1;
            mbar_wait(smem_u32(&smbar[s]), (k >> 1) & 1);

            const float* xs = sdata[s];
            #pragma unroll
            for (int rr = 0; rr < 4; rr++) {
                const int r   = warp * 4 + rr;
                const int lb  = slab[s][r];                  // smem bcast
                const float c = xs[r * 128 + lb];            // smem bcast
                const float4 v = reinterpret_cast<const float4*>(xs + r * 128)[lane];
                const float mg = MARGIN - c;
                wsum += fmaxf(mg + v.x, 0.0f) + fmaxf(mg + v.y, 0.0f)
                      + fmaxf(mg + v.z, 0.0f) + fmaxf(mg + v.w, 0.0f);
            }
            nrows += 4;

            tma_warps_sync();                // only the 8 TMA warps
            if (tid == 0 && k + 2 < cntT) {
                const int t = blockIdx.x + (k + 2) * NUM_BLOCKS;
                fence_async();
                const uint32_t mb = smem_u32(&smbar[s]);
                mbar_expect_tx(mb, TILE_BYTES + LAB_BYTES);
                bulk_g2s(smem_u32(&sdata[s][0]),
                         x + (size_t)t * TILE_FLOATS, TILE_BYTES, mb);
                bulk_g2s(smem_u32(&slab[s][0]),
                         labels + (size_t)t * RPT, LAB_BYTES, mb);
            }
        }
    } else {
        // ════ LDG streamer warps: rows [pRows, N), barrier-free ════
        const int lw     = warp - NTW;                            // 0..1
        const int wgid   = blockIdx.x * NLW + lw;                 // 0..1183
        const int nwarps = NUM_BLOCKS * NLW;                      // 1184
        const int nbL    = (N - pRows) / RPB;                     // 32768
        const int cntL   = (wgid < nbL) ? (nbL - 1 - wgid) / nwarps + 1 : 0;

        float4 vA[RPB], vB[RPB];
        float  cA[RPB], cB[RPB];

        auto prefetchL = [&](int m, float4* vv, float* cc) {
            const int bb = wgid + m * nwarps;
            const size_t rbase = (size_t)pRows + (size_t)bb * RPB;
            const int4 L = __ldg(&lab4[(pRows >> 2) + bb]);
            cc[0] = __ldg(&x[(rbase + 0) * 128 + L.x]);
            cc[1] = __ldg(&x[(rbase + 1) * 128 + L.y]);
            cc[2] = __ldg(&x[(rbase + 2) * 128 + L.z]);
            cc[3] = __ldg(&x[(rbase + 3) * 128 + L.w]);
            #pragma unroll
            for (int j = 0; j < RPB; j++)
                vv[j] = __ldcs(&x4[(rbase + j) * 32 + lane]);   // streaming
        };
        auto computeL = [&](const float4* vv, const float* cc) {
            #pragma unroll
            for (int j = 0; j < RPB; j++) {
                const float m = MARGIN - cc[j];
                wsum += fmaxf(m + vv[j].x, 0.0f) + fmaxf(m + vv[j].y, 0.0f)
                      + fmaxf(m + vv[j].z, 0.0f) + fmaxf(m + vv[j].w, 0.0f);
            }
            nrows += RPB;
        };

        if (cntL > 0) {
            prefetchL(0, vA, cA);
            for (int m = 0; m < cntL; m++) {
                if (m + 1 < cntL) {
                    if (m & 1) prefetchL(m + 1, vA, cA);
                    else       prefetchL(m + 1, vB, cB);
                }
                if (m & 1) computeL(vB, cB);
                else       computeL(vA, cA);
            }
        }
    }

    // ── Common epilogue ──
    #pragma unroll
    for (int o = 16; o > 0; o >>= 1)
        wsum += __shfl_down_sync(0xffffffffu, wsum, o);
    if (lane == 0) warp_sums[warp] = wsum - MARGIN * (float)nrows;

    __syncthreads();

    if (tid == 0) {
        double bsum = 0.0;
        #pragma unroll
        for (int wi = 0; wi < NWARPS; wi++) bsum += (double)warp_sums[wi];
        atomicAdd(&g_total, bsum);
        __threadfence();
        unsigned int t = atomicAdd(&g_count, 1u);
        is_last = (t == gridDim.x - 1);
    }
    __syncthreads();

    if (is_last && tid == 0) {
        const double total = g_total;
        // mean over N * (G-1) pairs, G = 128
        out[0] = (float)(total / ((double)N * 127.0));
        g_total = 0.0;
        g_count = 0u;
    }
}

extern "C" void kernel_launch(void* const* d_in, const int* in_sizes, int n_in,
                              void* d_out, int out_size)
{
    const float* x      = (const float*)d_in[0];
    const int*   labels = (const int*)d_in[1];
    float*       out    = (float*)d_out;

    const int N = in_sizes[1];                  // labels count = rows

    margin_loss_kernel<<<NUM_BLOCKS, NTHREADS>>>(x, labels, out, N);
}

// round 17
// speedup vs baseline: 1.9730x; 1.9730x over previous
#include <cuda_runtime.h>
#include <cstdint>

#define MARGIN 0.1f
#define RPT 16                          // rows per tile
#define TILE_FLOATS (RPT * 128)         // 2048
#define TILE_BYTES  (TILE_FLOATS * 4)   // 8192
#define LAB_BYTES   (RPT * 4)           // 64
#define NS 4                            // pipeline stages (2 per half)
#define NUM_BLOCKS 592                  // 148 SMs * 4 CTAs, single wave

// Persistent device scratch; reset by last block each call (graph-replay safe).
__device__ double       g_total = 0.0;
__device__ unsigned int g_count = 0u;

__device__ __forceinline__ uint32_t smem_u32(const void* p) {
    return (uint32_t)__cvta_generic_to_shared(p);
}
__device__ __forceinline__ void mbar_init(uint32_t a, uint32_t cnt) {
    asm volatile("mbarrier.init.shared.b64 [%0], %1;" :: "r"(a), "r"(cnt) : "memory");
}
__device__ __forceinline__ void mbar_expect_tx(uint32_t a, uint32_t bytes) {
    asm volatile("mbarrier.arrive.expect_tx.shared.b64 _, [%0], %1;"
                 :: "r"(a), "r"(bytes) : "memory");
}
__device__ __forceinline__ uint64_t mk_policy_evict_last() {
    uint64_t p;
    asm("createpolicy.fractional.L2::evict_last.b64 %0, 1.0;" : "=l"(p));
    return p;
}
__device__ __forceinline__ uint64_t mk_policy_evict_first() {
    uint64_t p;
    asm("createpolicy.fractional.L2::evict_first.b64 %0, 1.0;" : "=l"(p));
    return p;
}
__device__ __forceinline__ void bulk_g2s_pol(uint32_t dst, const void* src,
                                             uint32_t bytes, uint32_t mbar,
                                             uint64_t pol) {
    asm volatile(
        "cp.async.bulk.shared::cluster.global.mbarrier::complete_tx::bytes"
        ".L2::cache_hint [%0], [%1], %2, [%3], %4;"
        :: "r"(dst), "l"(src), "r"(bytes), "r"(mbar), "l"(pol) : "memory");
}
__device__ __forceinline__ void mbar_wait(uint32_t a, uint32_t parity) {
    asm volatile(
        "{\n\t"
        ".reg .pred P;\n\t"
        "WAIT_%=:\n\t"
        "mbarrier.try_wait.parity.acquire.cta.shared::cta.b64 P, [%0], %1, 0x989680;\n\t"
        "@P bra.uni DONE_%=;\n\t"
        "bra.uni WAIT_%=;\n\t"
        "DONE_%=:\n\t"
        "}"
        :: "r"(a), "r"(parity) : "memory");
}
__device__ __forceinline__ void fence_async() {
    asm volatile("fence.proxy.async.shared::cta;" ::: "memory");
}

__global__ void __launch_bounds__(256, 4)
margin_loss_kernel(const float* __restrict__ x,
                   const int* __restrict__ labels,   // int32 (JAX x64 disabled)
                   float* __restrict__ out,
                   int N)
{
    __shared__ __align__(128) float sdata[NS][TILE_FLOATS];   // 32 KB
    __shared__ __align__(16)  int   slab[NS][RPT];
    __shared__ __align__(8)   unsigned long long smbar[NS];
    __shared__ float warp_sums[8];
    __shared__ bool  is_last;

    const int tid  = threadIdx.x;
    const int warp = tid >> 5;
    const int lane = tid & 31;

    const int pRows = N >> 1;                 // persistent half  (evict_last)
    const int ntH   = pRows / RPT;            // tiles per half (8192)
    // This CTA's tiles per half (same formula both halves).
    const int cntH  = ((int)blockIdx.x < ntH)
                    ? (ntH - 1 - (int)blockIdx.x) / NUM_BLOCKS + 1 : 0;
    const int cnt   = cntH * 2;               // unified tile count

    if (tid == 0) {
        #pragma unroll
        for (int s = 0; s < NS; s++) mbar_init(smem_u32(&smbar[s]), 1);
        fence_async();
    }
    __syncthreads();

    const uint64_t polP = mk_policy_evict_last();   // persistent half
    const uint64_t polS = mk_policy_evict_first();  // streaming half

    // Tile k (unified order): even -> persistent half, odd -> streaming half.
    auto fill = [&](int s, int k) {
        const int half = k & 1;
        const int idx  = blockIdx.x + (k >> 1) * NUM_BLOCKS;
        const size_t rbase = (size_t)(half ? pRows : 0) + (size_t)idx * RPT;
        const uint64_t pol = half ? polS : polP;
        const uint32_t mb  = smem_u32(&smbar[s]);
        mbar_expect_tx(mb, TILE_BYTES + LAB_BYTES);
        bulk_g2s_pol(smem_u32(&sdata[s][0]), x + rbase * 128, TILE_BYTES, mb, pol);
        bulk_g2s_pol(smem_u32(&slab[s][0]),  labels + rbase,  LAB_BYTES,  mb, pol);
    };

    // Prologue: fill all stages.
    if (tid == 0) {
        #pragma unroll
        for (int s = 0; s < NS; s++)
            if (s < cnt) fill(s, s);
    }

    float wsum  = 0.0f;
    int   nrows = 0;

    for (int k = 0; k < cnt; k++) {
        const int s = k & (NS - 1);
        mbar_wait(smem_u32(&smbar[s]), (k >> 2) & 1);

        // 8 warps x 2 rows per tile; all operands from smem.
        const float* xs = sdata[s];
        #pragma unroll
        for (int rr = 0; rr < 2; rr++) {
            const int r   = warp * 2 + rr;
            const int lb  = slab[s][r];                  // smem bcast
            const float c = xs[r * 128 + lb];            // smem bcast
            const float4 v = reinterpret_cast<const float4*>(xs + r * 128)[lane];
            const float mg = MARGIN - c;
            wsum += fmaxf(mg + v.x, 0.0f) + fmaxf(mg + v.y, 0.0f)
                  + fmaxf(mg + v.z, 0.0f) + fmaxf(mg + v.w, 0.0f);
        }
        nrows += 2;

        __syncthreads();                  // stage s fully consumed
        if (tid == 0 && k + NS < cnt) {
            fence_async();
            fill(s, k + NS);
        }
    }

    // Warp reduction; remove the j==label MARGIN term per processed row.
    #pragma unroll
    for (int o = 16; o > 0; o >>= 1)
        wsum += __shfl_down_sync(0xffffffffu, wsum, o);
    if (lane == 0) warp_sums[warp] = wsum - MARGIN * (float)nrows;

    __syncthreads();

    if (tid == 0) {
        double bsum = 0.0;
        #pragma unroll
        for (int wi = 0; wi < 8; wi++) bsum += (double)warp_sums[wi];
        atomicAdd(&g_total, bsum);
        __threadfence();
        unsigned int t = atomicAdd(&g_count, 1u);
        is_last = (t == gridDim.x - 1);
    }
    __syncthreads();

    if (is_last && tid == 0) {
        const double total = g_total;
        // mean over N * (G-1) pairs, G = 128
        out[0] = (float)(total / ((double)N * 127.0));
        g_total = 0.0;
        g_count = 0u;
    }
}

extern "C" void kernel_launch(void* const* d_in, const int* in_sizes, int n_in,
                              void* d_out, int out_size)
{
    const float* x      = (const float*)d_in[0];
    const int*   labels = (const int*)d_in[1];
    float*       out    = (float*)d_out;

    const int N = in_sizes[1];                  // labels count = rows

    margin_loss_kernel<<<NUM_BLOCKS, 256>>>(x, labels, out, N);
}